// round 1
// baseline (speedup 1.0000x reference)
#include <cuda_runtime.h>
#include <math.h>

#define KTOT 2048
#define NJ   40
#define KC   64
#define KCP  68          // padded smem row stride (floats), 16B-aligned, conflict-safe
#define SMARGIN 0.31f

// Scratch (static device allocations are allowed; cudaMalloc is not)
__device__ float g_Wp[KTOT * NJ];          // packed [k][40] = [W_cls | W_fl] rows
__device__ float g_W12[KTOT * NJ];         // fused weight W_enc @ [W_cls|W_fl], k-major [k][40]
__device__ float g_c[NJ];                  // fused bias
__device__ float g_part[4 * 16384 * NJ];   // K-split partials (reused by both GEMM phases)

// ---------------------------------------------------------------------------
// Pack W_cls / W_fl rows into one [2048][40] k-major matrix
// ---------------------------------------------------------------------------
__global__ void pack_w_kernel(const float* __restrict__ Wcls, const float* __restrict__ Wfl) {
    int i = blockIdx.x * 256 + threadIdx.x;
    if (i < KTOT * NJ) {
        int m = i / NJ, j = i - m * NJ;
        g_Wp[i] = (j < 20) ? Wcls[m * 20 + j] : Wfl[m * 20 + (j - 20)];
    }
}

// ---------------------------------------------------------------------------
// Fused bias: c[j] = b_enc @ W_cls|W_fl + b_cls|b_fl
// ---------------------------------------------------------------------------
__global__ void bias_kernel(const float* __restrict__ benc, const float* __restrict__ Wcls,
                            const float* __restrict__ bcls, const float* __restrict__ Wfl,
                            const float* __restrict__ bfl) {
    int j = threadIdx.x;
    if (j >= NJ) return;
    const float* Wc = (j < 20) ? (Wcls + j) : (Wfl + (j - 20));
    float s0 = 0.f, s1 = 0.f, s2 = 0.f, s3 = 0.f;
    for (int m = 0; m < KTOT; m += 4) {
        s0 += benc[m + 0] * Wc[(m + 0) * 20];
        s1 += benc[m + 1] * Wc[(m + 1) * 20];
        s2 += benc[m + 2] * Wc[(m + 2) * 20];
        s3 += benc[m + 3] * Wc[(m + 3) * 20];
    }
    g_c[j] = ((j < 20) ? bcls[j] : bfl[j - 20]) + ((s0 + s1) + (s2 + s3));
}

// ---------------------------------------------------------------------------
// Skinny GEMM: out_part[split][M][40] += A[M][2048] @ W[2048][40] (K-split)
//   PHASE_B=false: A = W_enc (M=2048), W = g_Wp   -> builds W12 partials
//   PHASE_B=true : A = x     (M=16384), W = g_W12 -> builds logit partials
// Block: 256 threads, tile 64 rows x 40 cols, thread tile 2x5.
// Per 4k inner step: 2 LDS.128 (x) + 5 LDS.128 (w) + 40 FFMA  (85% FFMA mix)
// ---------------------------------------------------------------------------
template<int NSPLIT, bool PHASE_B>
__global__ __launch_bounds__(256, 3)
void skinny_gemm_kernel(const float* __restrict__ A, int M) {
    const float* __restrict__ W = PHASE_B ? g_W12 : g_Wp;
    const int ntiles = M >> 6;
    int tile  = blockIdx.x % ntiles;
    int split = blockIdx.x / ntiles;
    const int kspan = KTOT / NSPLIT;
    int kbeg = split * kspan;

    __shared__ float xs[64 * KCP];
    __shared__ float ws[NJ * KCP];

    int tid = threadIdx.x;
    int cg = tid & 7;       // 8 column groups of 5
    int rg = tid >> 3;      // 32 row groups of 2
    int j0 = cg * 5;
    int r0 = rg * 2;

    float acc[2][5];
#pragma unroll
    for (int r = 0; r < 2; r++)
#pragma unroll
        for (int j = 0; j < 5; j++) acc[r][j] = 0.f;

    const float* Abase = A + (size_t)(tile * 64) * KTOT + kbeg;

    for (int kc = 0; kc < kspan; kc += KC) {
        // --- stage x tile [64][64] (coalesced float4) ---
#pragma unroll
        for (int p = 0; p < 4; p++) {
            int idx = tid + p * 256;        // float4 index 0..1023
            int row = idx >> 4;
            int c4  = idx & 15;
            float4 v = *(const float4*)(Abase + (size_t)row * KTOT + kc + c4 * 4);
            *(float4*)&xs[row * KCP + c4 * 4] = v;
        }
        // --- stage w tile, transposed to ws[j][k] ---
        {
            const float* Wc = W + (size_t)(kbeg + kc) * NJ;
#pragma unroll
            for (int p = 0; p < 3; p++) {
                int idx = tid + p * 256;
                if (idx < (KC * NJ) / 4) {
                    float4 v = *(const float4*)(Wc + idx * 4);
                    float vv[4] = {v.x, v.y, v.z, v.w};
#pragma unroll
                    for (int e = 0; e < 4; e++) {
                        int el = idx * 4 + e;
                        int k = el / NJ;
                        int j = el - k * NJ;
                        ws[j * KCP + k] = vv[e];
                    }
                }
            }
        }
        __syncthreads();
        // --- compute ---
#pragma unroll
        for (int k4 = 0; k4 < KC / 4; k4++) {
            float4 x0 = *(const float4*)&xs[(r0 + 0) * KCP + k4 * 4];
            float4 x1 = *(const float4*)&xs[(r0 + 1) * KCP + k4 * 4];
#pragma unroll
            for (int jj = 0; jj < 5; jj++) {
                float4 w = *(const float4*)&ws[(j0 + jj) * KCP + k4 * 4];
                acc[0][jj] += x0.x * w.x; acc[0][jj] += x0.y * w.y;
                acc[0][jj] += x0.z * w.z; acc[0][jj] += x0.w * w.w;
                acc[1][jj] += x1.x * w.x; acc[1][jj] += x1.y * w.y;
                acc[1][jj] += x1.z * w.z; acc[1][jj] += x1.w * w.w;
            }
        }
        __syncthreads();
    }

    float* o = g_part + ((size_t)split * M + tile * 64) * NJ;
#pragma unroll
    for (int r = 0; r < 2; r++)
#pragma unroll
        for (int jj = 0; jj < 5; jj++)
            o[(r0 + r) * NJ + j0 + jj] = acc[r][jj];
}

// ---------------------------------------------------------------------------
// Reduce phase-A partials (8 splits) into g_W12
// ---------------------------------------------------------------------------
__global__ void reduce_w12_kernel() {
    int i = blockIdx.x * 256 + threadIdx.x;
    if (i < KTOT * NJ) {
        float s = 0.f;
#pragma unroll
        for (int p = 0; p < 8; p++) s += g_part[p * (KTOT * NJ) + i];
        g_W12[i] = s;
    }
}

// ---------------------------------------------------------------------------
// Epilogue: sum 4 partials + bias -> logits[40]; two softmaxes; threshold; write.
// Block handles 64 rows; coalesced partial reads + coalesced output writes.
// ---------------------------------------------------------------------------
__global__ __launch_bounds__(256)
void epilogue_kernel(float* __restrict__ out, int M) {
    __shared__ float sl[64 * 41];   // padded stride 41 -> conflict-free row reads
    __shared__ float sc[NJ];
    __shared__ float so[64 * 20];
    int tid = threadIdx.x;
    int r0 = blockIdx.x * 64;
    if (tid < NJ) sc[tid] = g_c[tid];
    __syncthreads();
    for (int idx = tid; idx < 64 * NJ; idx += 256) {
        int r = idx / NJ;
        int j = idx - r * NJ;
        float s = sc[j];
#pragma unroll
        for (int p = 0; p < 4; p++)
            s += g_part[((size_t)p * M + r0) * NJ + idx];
        sl[r * 41 + j] = s;
    }
    __syncthreads();
    if (tid < 64) {
        const float* l = &sl[tid * 41];
        // cls softmax
        float m1 = l[0];
#pragma unroll
        for (int j = 1; j < 20; j++) m1 = fmaxf(m1, l[j]);
        float e[20];
        float s1 = 0.f;
#pragma unroll
        for (int j = 0; j < 20; j++) { e[j] = expf(l[j] - m1); s1 += e[j]; }
        float inv = 1.f / s1;                 // == max softmax prob (exp(0)/s1)
        // flow softmax min -> tau
        float m2 = l[20], mn2 = l[20];
#pragma unroll
        for (int j = 21; j < 40; j++) { m2 = fmaxf(m2, l[j]); mn2 = fminf(mn2, l[j]); }
        float s2 = 0.f;
#pragma unroll
        for (int j = 20; j < 40; j++) s2 += expf(l[j] - m2);
        float tau = expf(mn2 - m2) / s2;
        float keep = (inv >= tau + SMARGIN) ? 1.f : 0.f;
        float scale = inv * keep;
#pragma unroll
        for (int j = 0; j < 20; j++) so[tid * 20 + j] = e[j] * scale;
    }
    __syncthreads();
    for (int idx = tid; idx < 64 * 20; idx += 256)
        out[(size_t)r0 * 20 + idx] = so[idx];
}

// ---------------------------------------------------------------------------
extern "C" void kernel_launch(void* const* d_in, const int* in_sizes, int n_in,
                              void* d_out, int out_size) {
    const float* x    = (const float*)d_in[0];
    const float* Wenc = (const float*)d_in[1];
    const float* benc = (const float*)d_in[2];
    const float* Wcls = (const float*)d_in[3];
    const float* bcls = (const float*)d_in[4];
    const float* Wfl  = (const float*)d_in[5];
    const float* bfl  = (const float*)d_in[6];
    float* out = (float*)d_out;
    int M = in_sizes[0] / KTOT;   // 16384

    // 1. pack [W_cls|W_fl] -> g_Wp
    pack_w_kernel<<<(KTOT * NJ + 255) / 256, 256>>>(Wcls, Wfl);
    // 2. W12 = W_enc @ g_Wp  (K-split 8 -> 256 CTAs)
    skinny_gemm_kernel<8, false><<<(KTOT / 64) * 8, 256>>>(Wenc, KTOT);
    // 3. reduce partials -> g_W12
    reduce_w12_kernel<<<(KTOT * NJ + 255) / 256, 256>>>();
    // 4. fused bias
    bias_kernel<<<1, 64>>>(benc, Wcls, bcls, Wfl, bfl);
    // 5. logits partials = x @ g_W12  (K-split 4 -> 1024 CTAs, the hot kernel)
    skinny_gemm_kernel<4, true><<<(M / 64) * 4, 256>>>(x, M);
    // 6. reduce + softmax x2 + threshold + write
    epilogue_kernel<<<M / 64, 256>>>(out, M);
}

// round 2
// speedup vs baseline: 1.3617x; 1.3617x over previous
#include <cuda_runtime.h>
#include <math.h>

#define KTOT 2048
#define NJ   40
#define KC   64
#define KCP  68          // padded smem row stride (floats), 16B-aligned, conflict-safe
#define SMARGIN 0.31f

// Scratch (static device allocations are allowed; cudaMalloc is not)
__device__ float g_Wp[KTOT * NJ];          // packed [k][40] = [W_cls | W_fl] rows
__device__ float g_W12[KTOT * NJ];         // fused weight W_enc @ [W_cls|W_fl], k-major [k][40]
__device__ float g_c[NJ];                  // fused bias
__device__ float g_part[4 * 16384 * NJ];   // K-split partials (reused by both GEMM phases)

// ---------------------------------------------------------------------------
// Pack W_cls / W_fl rows into one [2048][40] k-major matrix
// ---------------------------------------------------------------------------
__global__ void pack_w_kernel(const float* __restrict__ Wcls, const float* __restrict__ Wfl) {
    int i = blockIdx.x * 256 + threadIdx.x;
    if (i < KTOT * NJ) {
        int m = i / NJ, j = i - m * NJ;
        g_Wp[i] = (j < 20) ? Wcls[m * 20 + j] : Wfl[m * 20 + (j - 20)];
    }
}

// ---------------------------------------------------------------------------
// Fused bias: c[j] = b_enc @ Wp[:,j] + bcls|bfl.  One block per j, parallel
// tree reduction (fixes the 124us serial version from R1).
// ---------------------------------------------------------------------------
__global__ __launch_bounds__(256)
void bias_kernel(const float* __restrict__ benc, const float* __restrict__ bcls,
                 const float* __restrict__ bfl) {
    int j = blockIdx.x;          // 0..39
    int tid = threadIdx.x;
    float s = 0.f;
    // each thread: 8 strided elements, MLP=8
    for (int k = tid; k < KTOT; k += 256)
        s += benc[k] * g_Wp[k * NJ + j];
    // warp reduce
#pragma unroll
    for (int o = 16; o > 0; o >>= 1)
        s += __shfl_down_sync(0xffffffffu, s, o);
    __shared__ float sw[8];
    if ((tid & 31) == 0) sw[tid >> 5] = s;
    __syncthreads();
    if (tid == 0) {
        float t = sw[0] + sw[1] + sw[2] + sw[3] + sw[4] + sw[5] + sw[6] + sw[7];
        g_c[j] = t + ((j < 20) ? bcls[j] : bfl[j - 20]);
    }
}

// ---------------------------------------------------------------------------
// Skinny GEMM: out_part[split][M][40] += A[M][2048] @ W[2048][40] (K-split)
//   PHASE_B=false: A = W_enc (M=2048), W = g_Wp   -> builds W12 partials
//   PHASE_B=true : A = x     (M=16384), W = g_W12 -> builds logit partials
// Block: 256 threads, tile 64 rows x 40 cols, thread tile 2x5.
// ---------------------------------------------------------------------------
template<int NSPLIT, bool PHASE_B>
__global__ __launch_bounds__(256, 3)
void skinny_gemm_kernel(const float* __restrict__ A, int M) {
    const float* __restrict__ W = PHASE_B ? g_W12 : g_Wp;
    const int ntiles = M >> 6;
    int tile  = blockIdx.x % ntiles;
    int split = blockIdx.x / ntiles;
    const int kspan = KTOT / NSPLIT;
    int kbeg = split * kspan;

    __shared__ float xs[64 * KCP];
    __shared__ float ws[NJ * KCP];

    int tid = threadIdx.x;
    int cg = tid & 7;       // 8 column groups of 5
    int rg = tid >> 3;      // 32 row groups of 2
    int j0 = cg * 5;
    int r0 = rg * 2;

    float acc[2][5];
#pragma unroll
    for (int r = 0; r < 2; r++)
#pragma unroll
        for (int j = 0; j < 5; j++) acc[r][j] = 0.f;

    const float* Abase = A + (size_t)(tile * 64) * KTOT + kbeg;

    for (int kc = 0; kc < kspan; kc += KC) {
        // --- stage x tile [64][64] (coalesced float4) ---
#pragma unroll
        for (int p = 0; p < 4; p++) {
            int idx = tid + p * 256;        // float4 index 0..1023
            int row = idx >> 4;
            int c4  = idx & 15;
            float4 v = *(const float4*)(Abase + (size_t)row * KTOT + kc + c4 * 4);
            *(float4*)&xs[row * KCP + c4 * 4] = v;
        }
        // --- stage w tile, transposed to ws[j][k] ---
        {
            const float* Wc = W + (size_t)(kbeg + kc) * NJ;
#pragma unroll
            for (int p = 0; p < 3; p++) {
                int idx = tid + p * 256;
                if (idx < (KC * NJ) / 4) {
                    float4 v = *(const float4*)(Wc + idx * 4);
                    float vv[4] = {v.x, v.y, v.z, v.w};
#pragma unroll
                    for (int e = 0; e < 4; e++) {
                        int el = idx * 4 + e;
                        int k = el / NJ;
                        int j = el - k * NJ;
                        ws[j * KCP + k] = vv[e];
                    }
                }
            }
        }
        __syncthreads();
        // --- compute ---
#pragma unroll
        for (int k4 = 0; k4 < KC / 4; k4++) {
            float4 x0 = *(const float4*)&xs[(r0 + 0) * KCP + k4 * 4];
            float4 x1 = *(const float4*)&xs[(r0 + 1) * KCP + k4 * 4];
#pragma unroll
            for (int jj = 0; jj < 5; jj++) {
                float4 w = *(const float4*)&ws[(j0 + jj) * KCP + k4 * 4];
                acc[0][jj] += x0.x * w.x; acc[0][jj] += x0.y * w.y;
                acc[0][jj] += x0.z * w.z; acc[0][jj] += x0.w * w.w;
                acc[1][jj] += x1.x * w.x; acc[1][jj] += x1.y * w.y;
                acc[1][jj] += x1.z * w.z; acc[1][jj] += x1.w * w.w;
            }
        }
        __syncthreads();
    }

    float* o = g_part + ((size_t)split * M + tile * 64) * NJ;
#pragma unroll
    for (int r = 0; r < 2; r++)
#pragma unroll
        for (int jj = 0; jj < 5; jj++)
            o[(r0 + r) * NJ + j0 + jj] = acc[r][jj];
}

// ---------------------------------------------------------------------------
// Reduce phase-A partials (8 splits) into g_W12
// ---------------------------------------------------------------------------
__global__ void reduce_w12_kernel() {
    int i = blockIdx.x * 256 + threadIdx.x;
    if (i < KTOT * NJ) {
        float s = 0.f;
#pragma unroll
        for (int p = 0; p < 8; p++) s += g_part[p * (KTOT * NJ) + i];
        g_W12[i] = s;
    }
}

// ---------------------------------------------------------------------------
// Epilogue: sum 4 partials + bias -> logits[40]; two softmaxes; threshold; write.
// ---------------------------------------------------------------------------
__global__ __launch_bounds__(256)
void epilogue_kernel(float* __restrict__ out, int M) {
    __shared__ float sl[64 * 41];   // padded stride 41 -> conflict-free row reads
    __shared__ float sc[NJ];
    __shared__ float so[64 * 20];
    int tid = threadIdx.x;
    int r0 = blockIdx.x * 64;
    if (tid < NJ) sc[tid] = g_c[tid];
    __syncthreads();
    for (int idx = tid; idx < 64 * NJ; idx += 256) {
        int r = idx / NJ;
        int j = idx - r * NJ;
        float s = sc[j];
#pragma unroll
        for (int p = 0; p < 4; p++)
            s += g_part[((size_t)p * M + r0) * NJ + idx];
        sl[r * 41 + j] = s;
    }
    __syncthreads();
    if (tid < 64) {
        const float* l = &sl[tid * 41];
        // cls softmax
        float m1 = l[0];
#pragma unroll
        for (int j = 1; j < 20; j++) m1 = fmaxf(m1, l[j]);
        float e[20];
        float s1 = 0.f;
#pragma unroll
        for (int j = 0; j < 20; j++) { e[j] = expf(l[j] - m1); s1 += e[j]; }
        float inv = 1.f / s1;                 // == max softmax prob (exp(0)/s1)
        // flow softmax min -> tau
        float m2 = l[20], mn2 = l[20];
#pragma unroll
        for (int j = 21; j < 40; j++) { m2 = fmaxf(m2, l[j]); mn2 = fminf(mn2, l[j]); }
        float s2 = 0.f;
#pragma unroll
        for (int j = 20; j < 40; j++) s2 += expf(l[j] - m2);
        float tau = expf(mn2 - m2) / s2;
        float keep = (inv >= tau + SMARGIN) ? 1.f : 0.f;
        float scale = inv * keep;
#pragma unroll
        for (int j = 0; j < 20; j++) so[tid * 20 + j] = e[j] * scale;
    }
    __syncthreads();
    for (int idx = tid; idx < 64 * 20; idx += 256)
        out[(size_t)r0 * 20 + idx] = so[idx];
}

// ---------------------------------------------------------------------------
extern "C" void kernel_launch(void* const* d_in, const int* in_sizes, int n_in,
                              void* d_out, int out_size) {
    const float* x    = (const float*)d_in[0];
    const float* Wenc = (const float*)d_in[1];
    const float* benc = (const float*)d_in[2];
    const float* bcls = (const float*)d_in[4];
    const float* bfl  = (const float*)d_in[6];
    float* out = (float*)d_out;
    int M = in_sizes[0] / KTOT;   // 16384

    // 1. pack [W_cls|W_fl] -> g_Wp
    pack_w_kernel<<<(KTOT * NJ + 255) / 256, 256>>>((const float*)d_in[3], (const float*)d_in[5]);
    // 2. W12 = W_enc @ g_Wp  (K-split 8 -> 256 CTAs)
    skinny_gemm_kernel<8, false><<<(KTOT / 64) * 8, 256>>>(Wenc, KTOT);
    // 3. reduce partials -> g_W12
    reduce_w12_kernel<<<(KTOT * NJ + 255) / 256, 256>>>();
    // 4. fused bias (parallel reduction now)
    bias_kernel<<<NJ, 256>>>(benc, bcls, bfl);
    // 5. logits partials = x @ g_W12  (K-split 4 -> 1024 CTAs, the hot kernel)
    skinny_gemm_kernel<4, true><<<(M / 64) * 4, 256>>>(x, M);
    // 6. reduce + softmax x2 + threshold + write
    epilogue_kernel<<<M / 64, 256>>>(out, M);
}